// round 16
// baseline (speedup 1.0000x reference)
#include <cuda_runtime.h>
#include <cuda_bf16.h>
#include <math.h>
#include <stdint.h>

#define BATCH 2
#define SEQ   2048
#define NH    16
#define HD    128
#define HID   2048
#define NQKV  6144
#define MROWS 4096   // B*S
#define QKV_ELEMS ((size_t)BATCH * NH * SEQ * HD)

// ---------------- scratch (static device globals; no runtime alloc) ----------
__device__ unsigned short g_hid_h[(size_t)MROWS * HID], g_hid_l[(size_t)MROWS * HID];
__device__ unsigned short g_wqkv_h[(size_t)NQKV * HID], g_wqkv_l[(size_t)NQKV * HID];
__device__ unsigned short g_wout_h[(size_t)HID * HID], g_wout_l[(size_t)HID * HID];
__device__ unsigned short g_q_h[QKV_ELEMS], g_q_l[QKV_ELEMS];
__device__ unsigned short g_k_h[QKV_ELEMS], g_k_l[QKV_ELEMS];
__device__ unsigned short g_v_h[QKV_ELEMS], g_v_l[QKV_ELEMS];
__device__ unsigned short g_ctx_h[(size_t)MROWS * HID], g_ctx_l[(size_t)MROWS * HID];
__device__ float g_cos[SEQ * 64], g_sin[SEQ * 64];

// ---------------- helpers ----------------------------------------------------
__device__ __forceinline__ uint32_t smem_u32(const void* p) {
    return (uint32_t)__cvta_generic_to_shared(p);
}
__device__ __forceinline__ void ldm_x4(uint32_t (&r)[4], uint32_t addr) {
    asm volatile("ldmatrix.sync.aligned.m8n8.x4.shared.b16 {%0,%1,%2,%3}, [%4];\n"
        : "=r"(r[0]), "=r"(r[1]), "=r"(r[2]), "=r"(r[3]) : "r"(addr));
}
__device__ __forceinline__ void ldm_x4_t(uint32_t (&r)[4], uint32_t addr) {
    asm volatile("ldmatrix.sync.aligned.m8n8.x4.trans.shared.b16 {%0,%1,%2,%3}, [%4];\n"
        : "=r"(r[0]), "=r"(r[1]), "=r"(r[2]), "=r"(r[3]) : "r"(addr));
}
__device__ __forceinline__ void mma16816(float (&c)[4], const uint32_t (&a)[4],
                                         uint32_t b0, uint32_t b1) {
    asm volatile(
        "mma.sync.aligned.m16n8k16.row.col.f32.bf16.bf16.f32 "
        "{%0,%1,%2,%3}, {%4,%5,%6,%7}, {%8,%9}, {%0,%1,%2,%3};\n"
        : "+f"(c[0]), "+f"(c[1]), "+f"(c[2]), "+f"(c[3])
        : "r"(a[0]), "r"(a[1]), "r"(a[2]), "r"(a[3]), "r"(b0), "r"(b1));
}
__device__ __forceinline__ void split2(float x, unsigned short& h, unsigned short& l) {
    __nv_bfloat16 bh = __float2bfloat16_rn(x);
    h = __bfloat16_as_ushort(bh);
    l = __bfloat16_as_ushort(__float2bfloat16_rn(x - __bfloat162float(bh)));
}
__device__ __forceinline__ uint32_t pk(unsigned short a, unsigned short b) {
    return (uint32_t)a | ((uint32_t)b << 16);
}
__device__ __forceinline__ void cp16(uint32_t s, const void* g) {
    asm volatile("cp.async.cg.shared.global [%0], [%1], 16;\n" :: "r"(s), "l"(g));
}
__device__ __forceinline__ void cp_commit() {
    asm volatile("cp.async.commit_group;\n");
}
template <int N> __device__ __forceinline__ void cp_wait() {
    asm volatile("cp.async.wait_group %0;\n" :: "n"(N));
}

// ---------------- one-time fp32 -> bf16 hi/lo split --------------------------
__global__ void split_kernel(const float* __restrict__ src, int sel, int n4) {
    int i = blockIdx.x * 256 + threadIdx.x;
    if (i >= n4) return;
    unsigned short *dh, *dl;
    if (sel == 0)      { dh = g_hid_h;  dl = g_hid_l;  }
    else if (sel == 1) { dh = g_wqkv_h; dl = g_wqkv_l; }
    else               { dh = g_wout_h; dl = g_wout_l; }
    float4 v = ((const float4*)src)[i];
    unsigned short h0, h1, h2, h3, l0, l1, l2, l3;
    split2(v.x, h0, l0); split2(v.y, h1, l1);
    split2(v.z, h2, l2); split2(v.w, h3, l3);
    ((uint2*)dh)[i] = make_uint2(pk(h0, h1), pk(h2, h3));
    ((uint2*)dl)[i] = make_uint2(pk(l0, l1), pk(l2, l3));
}

// ---------------- RoPE tables ------------------------------------------------
__global__ void rope_table_kernel() {
    int idx = blockIdx.x * 256 + threadIdx.x;
    if (idx >= SEQ * 64) return;
    int s = idx >> 6, i = idx & 63;
    float inv = powf(10000.0f, -(float)(2 * i) / 128.0f);
    float ang = (float)s * inv;
    g_cos[idx] = cosf(ang);
    g_sin[idx] = sinf(ang);
}

// ---------------- split-bf16 tensor GEMM, 128x256 tile, cp.async 2-stage -----
// 8 warps (2M x 4N), warp tile 64x64. BK=32.
#define GLD 40
#define GEMM_SMEM (2 * (128 * GLD + 256 * GLD) * 2 * 2)   // 122880 B

template <int EPI>
__global__ __launch_bounds__(256, 1) void mma_gemm_kernel(
    const float* __restrict__ bias, float* __restrict__ out) {
    extern __shared__ unsigned short sm[];
    unsigned short* sAh = sm;                            // [2][128*GLD]
    unsigned short* sAl = sAh + 2 * 128 * GLD;
    unsigned short* sBh = sAl + 2 * 128 * GLD;           // [2][256*GLD]
    unsigned short* sBl = sBh + 2 * 256 * GLD;

    const unsigned short *Ah_g, *Al_g, *Bh_g, *Bl_g;
    if (EPI == 0) { Ah_g = g_hid_h; Al_g = g_hid_l; Bh_g = g_wqkv_h; Bl_g = g_wqkv_l; }
    else          { Ah_g = g_ctx_h; Al_g = g_ctx_l; Bh_g = g_wout_h; Bl_g = g_wout_l; }

    const int tid = threadIdx.x;
    const int warp = tid >> 5, lane = tid & 31;
    const int g = lane >> 2, tig = lane & 3;
    const int wm = (warp >> 2) * 64, wn = (warp & 3) * 64;
    const int bm = blockIdx.y * 128, bn = blockIdx.x * 256;

    float c[4][8][4];
#pragma unroll
    for (int mt = 0; mt < 4; mt++)
#pragma unroll
        for (int nt = 0; nt < 8; nt++)
#pragma unroll
            for (int q = 0; q < 4; q++) c[mt][nt][q] = 0.0f;

    // ldmatrix base addresses (stage 0)
    uint32_t aH[4], aL[4];
#pragma unroll
    for (int mt = 0; mt < 4; mt++) {
        int r = wm + mt * 16 + (lane & 15);
        int cc = (lane >> 4) << 3;
        aH[mt] = smem_u32(&sAh[r * GLD + cc]);
        aL[mt] = smem_u32(&sAl[r * GLD + cc]);
    }
    uint32_t bH[4], bL[4];
#pragma unroll
    for (int ntp = 0; ntp < 4; ntp++) {
        int r = wn + ntp * 16 + (lane & 7) + ((lane >> 4) << 3);
        int cc = ((lane >> 3) & 1) << 3;
        bH[ntp] = smem_u32(&sBh[r * GLD + cc]);
        bL[ntp] = smem_u32(&sBl[r * GLD + cc]);
    }

    auto load_stage = [&](int st, int k0) {
        const int offA = st * 128 * GLD;
        const int offB = st * 256 * GLD;
#pragma unroll
        for (int t = 0; t < 12; t++) {
            int idx = tid + t * 256;               // 0..3071, region uniform per t
            if (idx < 1024) {                      // A hi/lo
                int sub = idx & 511;
                int r = sub >> 2, col = (sub & 3) << 3;
                size_t ga = (size_t)(bm + r) * HID + k0 + col;
                if (idx < 512) cp16(smem_u32(&sAh[offA + r * GLD + col]), Ah_g + ga);
                else           cp16(smem_u32(&sAl[offA + r * GLD + col]), Al_g + ga);
            } else {                               // B hi/lo
                int sub = (idx - 1024) & 1023;
                int r = sub >> 2, col = (sub & 3) << 3;
                size_t gb = (size_t)(bn + r) * HID + k0 + col;
                if (idx < 2048) cp16(smem_u32(&sBh[offB + r * GLD + col]), Bh_g + gb);
                else            cp16(smem_u32(&sBl[offB + r * GLD + col]), Bl_g + gb);
            }
        }
    };

    load_stage(0, 0);
    cp_commit();

#pragma unroll 1
    for (int kt = 0; kt < HID / 32; kt++) {
        if (kt + 1 < HID / 32) load_stage((kt + 1) & 1, (kt + 1) * 32);
        cp_commit();
        cp_wait<1>();
        __syncthreads();

        const uint32_t stA = (uint32_t)((kt & 1) * 128 * GLD * 2);
        const uint32_t stB = (uint32_t)((kt & 1) * 256 * GLD * 2);
#pragma unroll
        for (int ks = 0; ks < 2; ks++) {
            const uint32_t ko = ks * 32;           // 16 bf16 = 32 bytes
            uint32_t Ah[4][4], Al[4][4];
#pragma unroll
            for (int mt = 0; mt < 4; mt++) {
                ldm_x4(Ah[mt], aH[mt] + stA + ko);
                ldm_x4(Al[mt], aL[mt] + stA + ko);
            }
#pragma unroll
            for (int half = 0; half < 2; half++) {
                uint32_t Bh[4][2], Bl[4][2];
#pragma unroll
                for (int p = 0; p < 2; p++) {
                    uint32_t t[4];
                    ldm_x4(t, bH[half * 2 + p] + stB + ko);
                    Bh[2 * p][0] = t[0]; Bh[2 * p][1] = t[1];
                    Bh[2 * p + 1][0] = t[2]; Bh[2 * p + 1][1] = t[3];
                    ldm_x4(t, bL[half * 2 + p] + stB + ko);
                    Bl[2 * p][0] = t[0]; Bl[2 * p][1] = t[1];
                    Bl[2 * p + 1][0] = t[2]; Bl[2 * p + 1][1] = t[3];
                }
#pragma unroll
                for (int mt = 0; mt < 4; mt++)
#pragma unroll
                    for (int nt = 0; nt < 4; nt++) {
                        float (&cc)[4] = c[mt][half * 4 + nt];
                        mma16816(cc, Ah[mt], Bh[nt][0], Bh[nt][1]);
                        mma16816(cc, Ah[mt], Bl[nt][0], Bl[nt][1]);
                        mma16816(cc, Al[mt], Bh[nt][0], Bh[nt][1]);
                    }
            }
        }
        __syncthreads();
    }

    // epilogue
#pragma unroll
    for (int nt = 0; nt < 8; nt++) {
        const int n0 = bn + wn + nt * 8 + 2 * tig;
        const float bv0 = bias[n0], bv1 = bias[n0 + 1];
#pragma unroll
        for (int mt = 0; mt < 4; mt++) {
#pragma unroll
            for (int half = 0; half < 2; half++) {
                int gm = bm + wm + mt * 16 + g + half * 8;
                float v0 = c[mt][nt][half * 2 + 0] + bv0;
                float v1 = c[mt][nt][half * 2 + 1] + bv1;
                if (EPI == 0) {
                    int seg = n0 >> 11;
                    int h = (n0 >> 7) & 15;
                    int d0 = n0 & 127;
                    int b = gm >> 11, s = gm & 2047;
                    unsigned short *dh, *dl;
                    if (seg < 2) {
                        float cc = g_cos[s * 64 + (d0 >> 1)];
                        float ss = g_sin[s * 64 + (d0 >> 1)];
                        float e = v0, o = v1;
                        v0 = e * cc - o * ss;
                        v1 = e * ss + o * cc;
                        if (seg == 0) { dh = g_q_h; dl = g_q_l; }
                        else          { dh = g_k_h; dl = g_k_l; }
                    } else { dh = g_v_h; dl = g_v_l; }
                    size_t off = (((size_t)b * NH + h) * SEQ + s) * HD + d0;
                    unsigned short h0, h1, l0, l1;
                    split2(v0, h0, l0); split2(v1, h1, l1);
                    *(uint32_t*)&dh[off] = pk(h0, h1);
                    *(uint32_t*)&dl[off] = pk(l0, l1);
                } else {
                    *(float2*)(out + (size_t)gm * HID + n0) = make_float2(v0, v1);
                }
            }
        }
    }
}

// ---------------- flash attention: row-owned warps, register-resident P ------
// Br=128 (8 warps x 16 rows), Bc=64, D=128. K/V double-buffered. (round-14)
#define QLD 136
#define KV_STG_B (64 * QLD * 2)
#define ATTN_SMEM ((2 * 128 * QLD + 8 * 64 * QLD) * 2)   // 208896 B

__global__ __launch_bounds__(256, 1) void attn_mma_kernel(const float* __restrict__ mask) {
    extern __shared__ unsigned short asm_[];
    unsigned short* sQh = asm_;
    unsigned short* sQl = sQh + 128 * QLD;
    unsigned short* sKh = sQl + 128 * QLD;
    unsigned short* sKl = sKh + 2 * 64 * QLD;
    unsigned short* sVh = sKl + 2 * 64 * QLD;
    unsigned short* sVl = sVh + 2 * 64 * QLD;

    const int tid = threadIdx.x;
    const int warp = tid >> 5, lane = tid & 31;
    const int g = lane >> 2, tig = lane & 3;
    const int q0 = blockIdx.x * 128;
    const int h = blockIdx.y, b = blockIdx.z;
    const size_t head_base = ((size_t)b * NH + h) * SEQ * HD;
    const float scale = 0.08838834764831845f;

#pragma unroll
    for (int i = 0; i < 8; i++) {
        int cch = tid + i * 256;
        int r = cch >> 4, col = (cch & 15) << 3;
        size_t ga = head_base + (size_t)(q0 + r) * HD + col;
        cp16(smem_u32(&sQh[r * QLD + col]), g_q_h + ga);
        cp16(smem_u32(&sQl[r * QLD + col]), g_q_l + ga);
    }
    cp_commit();

    auto load_kv = [&](int st, int k0) {
        int off = st * 64 * QLD;
#pragma unroll
        for (int i = 0; i < 4; i++) {
            int cch = tid + i * 256;
            int r = cch >> 4, col = (cch & 15) << 3;
            size_t ga = head_base + (size_t)(k0 + r) * HD + col;
            int so = off + r * QLD + col;
            cp16(smem_u32(&sKh[so]), g_k_h + ga);
            cp16(smem_u32(&sKl[so]), g_k_l + ga);
            cp16(smem_u32(&sVh[so]), g_v_h + ga);
            cp16(smem_u32(&sVl[so]), g_v_l + ga);
        }
    };
    load_kv(0, 0);
    cp_commit();

    const uint32_t qbH = smem_u32(&sQh[(warp * 16 + (lane & 15)) * QLD + ((lane >> 4) << 3)]);
    const uint32_t qbL = smem_u32(&sQl[(warp * 16 + (lane & 15)) * QLD + ((lane >> 4) << 3)]);
    uint32_t kbH[4], kbL[4], vbH[8], vbL[8];
#pragma unroll
    for (int ntp = 0; ntp < 4; ntp++) {
        int r = ntp * 16 + (lane & 7) + ((lane >> 4) << 3);
        int cc = ((lane >> 3) & 1) << 3;
        kbH[ntp] = smem_u32(&sKh[r * QLD + cc]);
        kbL[ntp] = smem_u32(&sKl[r * QLD + cc]);
    }
#pragma unroll
    for (int j = 0; j < 8; j++) {
        int vr = lane & 15;
        int vc = j * 16 + ((lane >> 4) << 3);
        vbH[j] = smem_u32(&sVh[vr * QLD + vc]);
        vbL[j] = smem_u32(&sVl[vr * QLD + vc]);
    }

    float co[16][4];
#pragma unroll
    for (int nt = 0; nt < 16; nt++)
#pragma unroll
        for (int q = 0; q < 4; q++) co[nt][q] = 0.0f;
    float m0 = -INFINITY, m1 = -INFINITY, l0 = 0.0f, l1 = 0.0f;

    const float* mrow = mask + (size_t)b * SEQ;

#pragma unroll 1
    for (int kt = 0; kt < SEQ / 64; kt++) {
        const int k0 = kt * 64;
        __syncthreads();
        if (kt + 1 < SEQ / 64) load_kv((kt + 1) & 1, (kt + 1) * 64);
        cp_commit();
        cp_wait<1>();
        __syncthreads();
        const uint32_t stg = (uint32_t)((kt & 1) * KV_STG_B);

        float cs[8][4];
#pragma unroll
        for (int nt = 0; nt < 8; nt++)
#pragma unroll
            for (int q = 0; q < 4; q++) cs[nt][q] = 0.0f;
#pragma unroll
        for (int k16 = 0; k16 < 8; k16++) {
            const uint32_t ko = k16 * 32;
            uint32_t Ahf[4], Alf[4];
            ldm_x4(Ahf, qbH + ko);
            ldm_x4(Alf, qbL + ko);
            uint32_t Bh[8][2], Bl[8][2];
#pragma unroll
            for (int ntp = 0; ntp < 4; ntp++) {
                uint32_t t[4];
                ldm_x4(t, kbH[ntp] + stg + ko);
                Bh[2 * ntp][0] = t[0]; Bh[2 * ntp][1] = t[1];
                Bh[2 * ntp + 1][0] = t[2]; Bh[2 * ntp + 1][1] = t[3];
                ldm_x4(t, kbL[ntp] + stg + ko);
                Bl[2 * ntp][0] = t[0]; Bl[2 * ntp][1] = t[1];
                Bl[2 * ntp + 1][0] = t[2]; Bl[2 * ntp + 1][1] = t[3];
            }
#pragma unroll
            for (int nt = 0; nt < 8; nt++) {
                mma16816(cs[nt], Ahf, Bh[nt][0], Bh[nt][1]);
                mma16816(cs[nt], Ahf, Bl[nt][0], Bl[nt][1]);
                mma16816(cs[nt], Alf, Bh[nt][0], Bh[nt][1]);
            }
        }

        float mx0 = -INFINITY, mx1 = -INFINITY;
#pragma unroll
        for (int nt = 0; nt < 8; nt++) {
            int cb = nt * 8 + 2 * tig;
            float mk0 = mrow[k0 + cb], mk1 = mrow[k0 + cb + 1];
            cs[nt][0] = cs[nt][0] * scale + mk0;
            cs[nt][1] = cs[nt][1] * scale + mk1;
            cs[nt][2] = cs[nt][2] * scale + mk0;
            cs[nt][3] = cs[nt][3] * scale + mk1;
            mx0 = fmaxf(mx0, fmaxf(cs[nt][0], cs[nt][1]));
            mx1 = fmaxf(mx1, fmaxf(cs[nt][2], cs[nt][3]));
        }
        mx0 = fmaxf(mx0, __shfl_xor_sync(0xffffffffu, mx0, 1));
        mx0 = fmaxf(mx0, __shfl_xor_sync(0xffffffffu, mx0, 2));
        mx1 = fmaxf(mx1, __shfl_xor_sync(0xffffffffu, mx1, 1));
        mx1 = fmaxf(mx1, __shfl_xor_sync(0xffffffffu, mx1, 2));
        const float mn0 = fmaxf(m0, mx0), mn1 = fmaxf(m1, mx1);
        const float al0 = __expf(m0 - mn0), al1 = __expf(m1 - mn1);
        m0 = mn0; m1 = mn1;

        float sum0 = 0.0f, sum1 = 0.0f;
#pragma unroll
        for (int nt = 0; nt < 8; nt++) {
            cs[nt][0] = __expf(cs[nt][0] - mn0);
            cs[nt][1] = __expf(cs[nt][1] - mn0);
            cs[nt][2] = __expf(cs[nt][2] - mn1);
            cs[nt][3] = __expf(cs[nt][3] - mn1);
            sum0 += cs[nt][0] + cs[nt][1];
            sum1 += cs[nt][2] + cs[nt][3];
        }
        sum0 += __shfl_xor_sync(0xffffffffu, sum0, 1);
        sum0 += __shfl_xor_sync(0xffffffffu, sum0, 2);
        sum1 += __shfl_xor_sync(0xffffffffu, sum1, 1);
        sum1 += __shfl_xor_sync(0xffffffffu, sum1, 2);
        l0 = l0 * al0 + sum0;
        l1 = l1 * al1 + sum1;

#pragma unroll
        for (int nt = 0; nt < 16; nt++) {
            co[nt][0] *= al0; co[nt][1] *= al0;
            co[nt][2] *= al1; co[nt][3] *= al1;
        }
#pragma unroll
        for (int kb = 0; kb < 4; kb++) {
            uint32_t paH[4], paL[4];
            {
                unsigned short h0, h1, l0s, l1s;
                split2(cs[2 * kb][0], h0, l0s); split2(cs[2 * kb][1], h1, l1s);
                paH[0] = pk(h0, h1); paL[0] = pk(l0s, l1s);
                split2(cs[2 * kb][2], h0, l0s); split2(cs[2 * kb][3], h1, l1s);
                paH[1] = pk(h0, h1); paL[1] = pk(l0s, l1s);
                split2(cs[2 * kb + 1][0], h0, l0s); split2(cs[2 * kb + 1][1], h1, l1s);
                paH[2] = pk(h0, h1); paL[2] = pk(l0s, l1s);
                split2(cs[2 * kb + 1][2], h0, l0s); split2(cs[2 * kb + 1][3], h1, l1s);
                paH[3] = pk(h0, h1); paL[3] = pk(l0s, l1s);
            }
            const uint32_t vko = stg + (uint32_t)kb * 16 * QLD * 2;
#pragma unroll
            for (int half = 0; half < 2; half++) {
                uint32_t Bh[8][2], Bl[8][2];
#pragma unroll
                for (int jp = 0; jp < 4; jp++) {
                    uint32_t t[4];
                    ldm_x4_t(t, vbH[half * 4 + jp] + vko);
                    Bh[2 * jp][0] = t[0]; Bh[2 * jp][1] = t[1];
                    Bh[2 * jp + 1][0] = t[2]; Bh[2 * jp + 1][1] = t[3];
                    ldm_x4_t(t, vbL[half * 4 + jp] + vko);
                    Bl[2 * jp][0] = t[0]; Bl[2 * jp][1] = t[1];
                    Bl[2 * jp + 1][0] = t[2]; Bl[2 * jp + 1][1] = t[3];
                }
#pragma unroll
                for (int nt = 0; nt < 8; nt++) {
                    int ng = half * 8 + nt;
                    mma16816(co[ng], paH, Bh[nt][0], Bh[nt][1]);
                    mma16816(co[ng], paH, Bl[nt][0], Bl[nt][1]);
                    mma16816(co[ng], paL, Bh[nt][0], Bh[nt][1]);
                }
            }
        }
    }

    const float inv0 = 1.0f / l0, inv1 = 1.0f / l1;
    const int r0 = warp * 16 + g, r1 = r0 + 8;
#pragma unroll
    for (int nt = 0; nt < 16; nt++) {
        int col = h * HD + nt * 8 + 2 * tig;
        size_t base0 = (size_t)(b * SEQ + q0 + r0) * HID + col;
        size_t base1 = (size_t)(b * SEQ + q0 + r1) * HID + col;
        unsigned short h0, h1, l0s, l1s;
        split2(co[nt][0] * inv0, h0, l0s);
        split2(co[nt][1] * inv0, h1, l1s);
        *(uint32_t*)&g_ctx_h[base0] = pk(h0, h1);
        *(uint32_t*)&g_ctx_l[base0] = pk(l0s, l1s);
        split2(co[nt][2] * inv1, h0, l0s);
        split2(co[nt][3] * inv1, h1, l1s);
        *(uint32_t*)&g_ctx_h[base1] = pk(h0, h1);
        *(uint32_t*)&g_ctx_l[base1] = pk(l0s, l1s);
    }
}

// ---------------- launcher ---------------------------------------------------
extern "C" void kernel_launch(void* const* d_in, const int* in_sizes, int n_in,
                              void* d_out, int out_size) {
    const float* hidden = (const float*)d_in[0];
    const float* mask   = (const float*)d_in[1];
    const float* Wqkv   = (const float*)d_in[2];
    const float* bqkv   = (const float*)d_in[3];
    const float* Wout   = (const float*)d_in[4];
    const float* bout   = (const float*)d_in[5];
    float* out = (float*)d_out;

    split_kernel<<<(MROWS * HID / 4 + 255) / 256, 256>>>(hidden, 0, MROWS * HID / 4);
    split_kernel<<<(NQKV * HID / 4 + 255) / 256, 256>>>(Wqkv, 1, NQKV * HID / 4);
    split_kernel<<<(HID * HID / 4 + 255) / 256, 256>>>(Wout, 2, HID * HID / 4);
    rope_table_kernel<<<512, 256>>>();

    cudaFuncSetAttribute(mma_gemm_kernel<0>,
                         cudaFuncAttributeMaxDynamicSharedMemorySize, GEMM_SMEM);
    cudaFuncSetAttribute(mma_gemm_kernel<1>,
                         cudaFuncAttributeMaxDynamicSharedMemorySize, GEMM_SMEM);

    mma_gemm_kernel<0><<<dim3(NQKV / 256, MROWS / 128), 256, GEMM_SMEM>>>(bqkv, nullptr);

    cudaFuncSetAttribute(attn_mma_kernel,
                         cudaFuncAttributeMaxDynamicSharedMemorySize, ATTN_SMEM);
    attn_mma_kernel<<<dim3(SEQ / 128, NH, BATCH), 256, ATTN_SMEM>>>(mask);

    mma_gemm_kernel<1><<<dim3(HID / 256, MROWS / 128), 256, GEMM_SMEM>>>(bout, out);
}

// round 17
// speedup vs baseline: 1.4700x; 1.4700x over previous
#include <cuda_runtime.h>
#include <cuda_bf16.h>
#include <math.h>
#include <stdint.h>

#define BATCH 2
#define SEQ   2048
#define NH    16
#define HD    128
#define HID   2048
#define NQKV  6144
#define MROWS 4096   // B*S
#define QKV_ELEMS ((size_t)BATCH * NH * SEQ * HD)

// ---------------- scratch (static device globals; no runtime alloc) ----------
__device__ unsigned short g_hid_h[(size_t)MROWS * HID], g_hid_l[(size_t)MROWS * HID];
__device__ unsigned short g_wqkv_h[(size_t)NQKV * HID], g_wqkv_l[(size_t)NQKV * HID];
__device__ unsigned short g_wout_h[(size_t)HID * HID], g_wout_l[(size_t)HID * HID];
__device__ unsigned short g_q_h[QKV_ELEMS], g_q_l[QKV_ELEMS];
__device__ unsigned short g_k_h[QKV_ELEMS], g_k_l[QKV_ELEMS];
__device__ unsigned short g_v_h[QKV_ELEMS], g_v_l[QKV_ELEMS];
__device__ unsigned short g_ctx_h[(size_t)MROWS * HID], g_ctx_l[(size_t)MROWS * HID];
__device__ float g_cos[SEQ * 64], g_sin[SEQ * 64];

// ---------------- helpers ----------------------------------------------------
__device__ __forceinline__ uint32_t smem_u32(const void* p) {
    return (uint32_t)__cvta_generic_to_shared(p);
}
__device__ __forceinline__ void ldm_x4(uint32_t (&r)[4], uint32_t addr) {
    asm volatile("ldmatrix.sync.aligned.m8n8.x4.shared.b16 {%0,%1,%2,%3}, [%4];\n"
        : "=r"(r[0]), "=r"(r[1]), "=r"(r[2]), "=r"(r[3]) : "r"(addr));
}
__device__ __forceinline__ void ldm_x4_t(uint32_t (&r)[4], uint32_t addr) {
    asm volatile("ldmatrix.sync.aligned.m8n8.x4.trans.shared.b16 {%0,%1,%2,%3}, [%4];\n"
        : "=r"(r[0]), "=r"(r[1]), "=r"(r[2]), "=r"(r[3]) : "r"(addr));
}
__device__ __forceinline__ void mma16816(float (&c)[4], const uint32_t (&a)[4],
                                         uint32_t b0, uint32_t b1) {
    asm volatile(
        "mma.sync.aligned.m16n8k16.row.col.f32.bf16.bf16.f32 "
        "{%0,%1,%2,%3}, {%4,%5,%6,%7}, {%8,%9}, {%0,%1,%2,%3};\n"
        : "+f"(c[0]), "+f"(c[1]), "+f"(c[2]), "+f"(c[3])
        : "r"(a[0]), "r"(a[1]), "r"(a[2]), "r"(a[3]), "r"(b0), "r"(b1));
}
__device__ __forceinline__ void split2(float x, unsigned short& h, unsigned short& l) {
    __nv_bfloat16 bh = __float2bfloat16_rn(x);
    h = __bfloat16_as_ushort(bh);
    l = __bfloat16_as_ushort(__float2bfloat16_rn(x - __bfloat162float(bh)));
}
__device__ __forceinline__ uint32_t pk(unsigned short a, unsigned short b) {
    return (uint32_t)a | ((uint32_t)b << 16);
}
__device__ __forceinline__ void cp16(uint32_t s, const void* g) {
    asm volatile("cp.async.cg.shared.global [%0], [%1], 16;\n" :: "r"(s), "l"(g));
}
__device__ __forceinline__ void cp_commit() {
    asm volatile("cp.async.commit_group;\n");
}
template <int N> __device__ __forceinline__ void cp_wait() {
    asm volatile("cp.async.wait_group %0;\n" :: "n"(N));
}

// ---------------- one-time fp32 -> bf16 hi/lo split --------------------------
__global__ void split_kernel(const float* __restrict__ src, int sel, int n4) {
    int i = blockIdx.x * 256 + threadIdx.x;
    if (i >= n4) return;
    unsigned short *dh, *dl;
    if (sel == 0)      { dh = g_hid_h;  dl = g_hid_l;  }
    else if (sel == 1) { dh = g_wqkv_h; dl = g_wqkv_l; }
    else               { dh = g_wout_h; dl = g_wout_l; }
    float4 v = ((const float4*)src)[i];
    unsigned short h0, h1, h2, h3, l0, l1, l2, l3;
    split2(v.x, h0, l0); split2(v.y, h1, l1);
    split2(v.z, h2, l2); split2(v.w, h3, l3);
    ((uint2*)dh)[i] = make_uint2(pk(h0, h1), pk(h2, h3));
    ((uint2*)dl)[i] = make_uint2(pk(l0, l1), pk(l2, l3));
}

// ---------------- RoPE tables ------------------------------------------------
__global__ void rope_table_kernel() {
    int idx = blockIdx.x * 256 + threadIdx.x;
    if (idx >= SEQ * 64) return;
    int s = idx >> 6, i = idx & 63;
    float inv = powf(10000.0f, -(float)(2 * i) / 128.0f);
    float ang = (float)s * inv;
    g_cos[idx] = cosf(ang);
    g_sin[idx] = sinf(ang);
}

// ---------------- split-bf16 tensor GEMM, 128x128 tile, cp.async 3-stage -----
// 8 warps (2M x 4N), warp tile 64x32. BK=32. (round-11 compute, deeper pipeline)
#define GLD 40
#define NSTG 3
#define GEMM_SMEM (NSTG * 128 * GLD * 2 * 4)   // 122880 B

template <int EPI>
__global__ __launch_bounds__(256, 1) void mma_gemm_kernel(
    const float* __restrict__ bias, float* __restrict__ out) {
    extern __shared__ unsigned short sm[];
    unsigned short* sAh = sm;                            // [NSTG][128*GLD]
    unsigned short* sAl = sAh + NSTG * 128 * GLD;
    unsigned short* sBh = sAl + NSTG * 128 * GLD;
    unsigned short* sBl = sBh + NSTG * 128 * GLD;

    const unsigned short *Ah_g, *Al_g, *Bh_g, *Bl_g;
    if (EPI == 0) { Ah_g = g_hid_h; Al_g = g_hid_l; Bh_g = g_wqkv_h; Bl_g = g_wqkv_l; }
    else          { Ah_g = g_ctx_h; Al_g = g_ctx_l; Bh_g = g_wout_h; Bl_g = g_wout_l; }

    const int tid = threadIdx.x;
    const int warp = tid >> 5, lane = tid & 31;
    const int g = lane >> 2, tig = lane & 3;
    const int wm = (warp >> 2) * 64, wn = (warp & 3) * 32;
    const int bm = blockIdx.y * 128, bn = blockIdx.x * 128;

    float c[4][4][4];
#pragma unroll
    for (int mt = 0; mt < 4; mt++)
#pragma unroll
        for (int nt = 0; nt < 4; nt++)
#pragma unroll
            for (int q = 0; q < 4; q++) c[mt][nt][q] = 0.0f;

    // ldmatrix base addresses (stage 0)
    uint32_t aH[4], aL[4];
#pragma unroll
    for (int mt = 0; mt < 4; mt++) {
        int r = wm + mt * 16 + (lane & 15);
        int cc = (lane >> 4) << 3;
        aH[mt] = smem_u32(&sAh[r * GLD + cc]);
        aL[mt] = smem_u32(&sAl[r * GLD + cc]);
    }
    uint32_t bH[2], bL[2];
#pragma unroll
    for (int ntp = 0; ntp < 2; ntp++) {
        int r = wn + ntp * 16 + (lane & 7) + ((lane >> 4) << 3);
        int cc = ((lane >> 3) & 1) << 3;
        bH[ntp] = smem_u32(&sBh[r * GLD + cc]);
        bL[ntp] = smem_u32(&sBl[r * GLD + cc]);
    }

    auto load_stage = [&](int st, int k0) {
        int off = st * 128 * GLD;
#pragma unroll
        for (int i = 0; i < 2; i++) {
            int cch = tid + i * 256;
            int r = cch >> 2, col = (cch & 3) << 3;
            size_t ga = (size_t)(bm + r) * HID + k0 + col;
            size_t gb = (size_t)(bn + r) * HID + k0 + col;
            int so = off + r * GLD + col;
            cp16(smem_u32(&sAh[so]), Ah_g + ga);
            cp16(smem_u32(&sAl[so]), Al_g + ga);
            cp16(smem_u32(&sBh[so]), Bh_g + gb);
            cp16(smem_u32(&sBl[so]), Bl_g + gb);
        }
    };

    load_stage(0, 0);
    cp_commit();
    load_stage(1, 32);
    cp_commit();

    const int NT = HID / 32;   // 64 k-tiles
    int stage = 0;
#pragma unroll 1
    for (int kt = 0; kt < NT; kt++) {
        if (kt + 2 < NT) load_stage((stage + 2) % NSTG, (kt + 2) * 32);
        cp_commit();
        cp_wait<2>();
        __syncthreads();

        const uint32_t stb = (uint32_t)(stage * 128 * GLD * 2);
#pragma unroll
        for (int ks = 0; ks < 2; ks++) {
            const uint32_t ko = stb + ks * 32;
            uint32_t Ah[4][4], Al[4][4];
#pragma unroll
            for (int mt = 0; mt < 4; mt++) {
                ldm_x4(Ah[mt], aH[mt] + ko);
                ldm_x4(Al[mt], aL[mt] + ko);
            }
            uint32_t Bh[4][2], Bl[4][2];
#pragma unroll
            for (int ntp = 0; ntp < 2; ntp++) {
                uint32_t t[4];
                ldm_x4(t, bH[ntp] + ko);
                Bh[2 * ntp][0] = t[0]; Bh[2 * ntp][1] = t[1];
                Bh[2 * ntp + 1][0] = t[2]; Bh[2 * ntp + 1][1] = t[3];
                ldm_x4(t, bL[ntp] + ko);
                Bl[2 * ntp][0] = t[0]; Bl[2 * ntp][1] = t[1];
                Bl[2 * ntp + 1][0] = t[2]; Bl[2 * ntp + 1][1] = t[3];
            }
#pragma unroll
            for (int mt = 0; mt < 4; mt++)
#pragma unroll
                for (int nt = 0; nt < 4; nt++) {
                    mma16816(c[mt][nt], Ah[mt], Bh[nt][0], Bh[nt][1]);
                    mma16816(c[mt][nt], Ah[mt], Bl[nt][0], Bl[nt][1]);
                    mma16816(c[mt][nt], Al[mt], Bh[nt][0], Bh[nt][1]);
                }
        }
        __syncthreads();
        stage = (stage + 1) % NSTG;
    }

    // epilogue
#pragma unroll
    for (int nt = 0; nt < 4; nt++) {
        const int n0 = bn + wn + nt * 8 + 2 * tig;
        const float bv0 = bias[n0], bv1 = bias[n0 + 1];
#pragma unroll
        for (int mt = 0; mt < 4; mt++) {
#pragma unroll
            for (int half = 0; half < 2; half++) {
                int gm = bm + wm + mt * 16 + g + half * 8;
                float v0 = c[mt][nt][half * 2 + 0] + bv0;
                float v1 = c[mt][nt][half * 2 + 1] + bv1;
                if (EPI == 0) {
                    int seg = n0 >> 11;
                    int h = (n0 >> 7) & 15;
                    int d0 = n0 & 127;
                    int b = gm >> 11, s = gm & 2047;
                    unsigned short *dh, *dl;
                    if (seg < 2) {
                        float cc = g_cos[s * 64 + (d0 >> 1)];
                        float ss = g_sin[s * 64 + (d0 >> 1)];
                        float e = v0, o = v1;
                        v0 = e * cc - o * ss;
                        v1 = e * ss + o * cc;
                        if (seg == 0) { dh = g_q_h; dl = g_q_l; }
                        else          { dh = g_k_h; dl = g_k_l; }
                    } else { dh = g_v_h; dl = g_v_l; }
                    size_t off = (((size_t)b * NH + h) * SEQ + s) * HD + d0;
                    unsigned short h0, h1, l0, l1;
                    split2(v0, h0, l0); split2(v1, h1, l1);
                    *(uint32_t*)&dh[off] = pk(h0, h1);
                    *(uint32_t*)&dl[off] = pk(l0, l1);
                } else {
                    *(float2*)(out + (size_t)gm * HID + n0) = make_float2(v0, v1);
                }
            }
        }
    }
}

// ---------------- flash attention: row-owned warps, register-resident P ------
// Br=128 (8 warps x 16 rows), Bc=64, D=128. K/V double-buffered. (round-14)
#define QLD 136
#define KV_STG_B (64 * QLD * 2)
#define ATTN_SMEM ((2 * 128 * QLD + 8 * 64 * QLD) * 2)   // 208896 B

__global__ __launch_bounds__(256, 1) void attn_mma_kernel(const float* __restrict__ mask) {
    extern __shared__ unsigned short asm_[];
    unsigned short* sQh = asm_;
    unsigned short* sQl = sQh + 128 * QLD;
    unsigned short* sKh = sQl + 128 * QLD;
    unsigned short* sKl = sKh + 2 * 64 * QLD;
    unsigned short* sVh = sKl + 2 * 64 * QLD;
    unsigned short* sVl = sVh + 2 * 64 * QLD;

    const int tid = threadIdx.x;
    const int warp = tid >> 5, lane = tid & 31;
    const int g = lane >> 2, tig = lane & 3;
    const int q0 = blockIdx.x * 128;
    const int h = blockIdx.y, b = blockIdx.z;
    const size_t head_base = ((size_t)b * NH + h) * SEQ * HD;
    const float scale = 0.08838834764831845f;

#pragma unroll
    for (int i = 0; i < 8; i++) {
        int cch = tid + i * 256;
        int r = cch >> 4, col = (cch & 15) << 3;
        size_t ga = head_base + (size_t)(q0 + r) * HD + col;
        cp16(smem_u32(&sQh[r * QLD + col]), g_q_h + ga);
        cp16(smem_u32(&sQl[r * QLD + col]), g_q_l + ga);
    }
    cp_commit();

    auto load_kv = [&](int st, int k0) {
        int off = st * 64 * QLD;
#pragma unroll
        for (int i = 0; i < 4; i++) {
            int cch = tid + i * 256;
            int r = cch >> 4, col = (cch & 15) << 3;
            size_t ga = head_base + (size_t)(k0 + r) * HD + col;
            int so = off + r * QLD + col;
            cp16(smem_u32(&sKh[so]), g_k_h + ga);
            cp16(smem_u32(&sKl[so]), g_k_l + ga);
            cp16(smem_u32(&sVh[so]), g_v_h + ga);
            cp16(smem_u32(&sVl[so]), g_v_l + ga);
        }
    };
    load_kv(0, 0);
    cp_commit();

    const uint32_t qbH = smem_u32(&sQh[(warp * 16 + (lane & 15)) * QLD + ((lane >> 4) << 3)]);
    const uint32_t qbL = smem_u32(&sQl[(warp * 16 + (lane & 15)) * QLD + ((lane >> 4) << 3)]);
    uint32_t kbH[4], kbL[4], vbH[8], vbL[8];
#pragma unroll
    for (int ntp = 0; ntp < 4; ntp++) {
        int r = ntp * 16 + (lane & 7) + ((lane >> 4) << 3);
        int cc = ((lane >> 3) & 1) << 3;
        kbH[ntp] = smem_u32(&sKh[r * QLD + cc]);
        kbL[ntp] = smem_u32(&sKl[r * QLD + cc]);
    }
#pragma unroll
    for (int j = 0; j < 8; j++) {
        int vr = lane & 15;
        int vc = j * 16 + ((lane >> 4) << 3);
        vbH[j] = smem_u32(&sVh[vr * QLD + vc]);
        vbL[j] = smem_u32(&sVl[vr * QLD + vc]);
    }

    float co[16][4];
#pragma unroll
    for (int nt = 0; nt < 16; nt++)
#pragma unroll
        for (int q = 0; q < 4; q++) co[nt][q] = 0.0f;
    float m0 = -INFINITY, m1 = -INFINITY, l0 = 0.0f, l1 = 0.0f;

    const float* mrow = mask + (size_t)b * SEQ;

#pragma unroll 1
    for (int kt = 0; kt < SEQ / 64; kt++) {
        const int k0 = kt * 64;
        __syncthreads();
        if (kt + 1 < SEQ / 64) load_kv((kt + 1) & 1, (kt + 1) * 64);
        cp_commit();
        cp_wait<1>();
        __syncthreads();
        const uint32_t stg = (uint32_t)((kt & 1) * KV_STG_B);

        float cs[8][4];
#pragma unroll
        for (int nt = 0; nt < 8; nt++)
#pragma unroll
            for (int q = 0; q < 4; q++) cs[nt][q] = 0.0f;
#pragma unroll
        for (int k16 = 0; k16 < 8; k16++) {
            const uint32_t ko = k16 * 32;
            uint32_t Ahf[4], Alf[4];
            ldm_x4(Ahf, qbH + ko);
            ldm_x4(Alf, qbL + ko);
            uint32_t Bh[8][2], Bl[8][2];
#pragma unroll
            for (int ntp = 0; ntp < 4; ntp++) {
                uint32_t t[4];
                ldm_x4(t, kbH[ntp] + stg + ko);
                Bh[2 * ntp][0] = t[0]; Bh[2 * ntp][1] = t[1];
                Bh[2 * ntp + 1][0] = t[2]; Bh[2 * ntp + 1][1] = t[3];
                ldm_x4(t, kbL[ntp] + stg + ko);
                Bl[2 * ntp][0] = t[0]; Bl[2 * ntp][1] = t[1];
                Bl[2 * ntp + 1][0] = t[2]; Bl[2 * ntp + 1][1] = t[3];
            }
#pragma unroll
            for (int nt = 0; nt < 8; nt++) {
                mma16816(cs[nt], Ahf, Bh[nt][0], Bh[nt][1]);
                mma16816(cs[nt], Ahf, Bl[nt][0], Bl[nt][1]);
                mma16816(cs[nt], Alf, Bh[nt][0], Bh[nt][1]);
            }
        }

        float mx0 = -INFINITY, mx1 = -INFINITY;
#pragma unroll
        for (int nt = 0; nt < 8; nt++) {
            int cb = nt * 8 + 2 * tig;
            float mk0 = mrow[k0 + cb], mk1 = mrow[k0 + cb + 1];
            cs[nt][0] = cs[nt][0] * scale + mk0;
            cs[nt][1] = cs[nt][1] * scale + mk1;
            cs[nt][2] = cs[nt][2] * scale + mk0;
            cs[nt][3] = cs[nt][3] * scale + mk1;
            mx0 = fmaxf(mx0, fmaxf(cs[nt][0], cs[nt][1]));
            mx1 = fmaxf(mx1, fmaxf(cs[nt][2], cs[nt][3]));
        }
        mx0 = fmaxf(mx0, __shfl_xor_sync(0xffffffffu, mx0, 1));
        mx0 = fmaxf(mx0, __shfl_xor_sync(0xffffffffu, mx0, 2));
        mx1 = fmaxf(mx1, __shfl_xor_sync(0xffffffffu, mx1, 1));
        mx1 = fmaxf(mx1, __shfl_xor_sync(0xffffffffu, mx1, 2));
        const float mn0 = fmaxf(m0, mx0), mn1 = fmaxf(m1, mx1);
        const float al0 = __expf(m0 - mn0), al1 = __expf(m1 - mn1);
        m0 = mn0; m1 = mn1;

        float sum0 = 0.0f, sum1 = 0.0f;
#pragma unroll
        for (int nt = 0; nt < 8; nt++) {
            cs[nt][0] = __expf(cs[nt][0] - mn0);
            cs[nt][1] = __expf(cs[nt][1] - mn0);
            cs[nt][2] = __expf(cs[nt][2] - mn1);
            cs[nt][3] = __expf(cs[nt][3] - mn1);
            sum0 += cs[nt][0] + cs[nt][1];
            sum1 += cs[nt][2] + cs[nt][3];
        }
        sum0 += __shfl_xor_sync(0xffffffffu, sum0, 1);
        sum0 += __shfl_xor_sync(0xffffffffu, sum0, 2);
        sum1 += __shfl_xor_sync(0xffffffffu, sum1, 1);
        sum1 += __shfl_xor_sync(0xffffffffu, sum1, 2);
        l0 = l0 * al0 + sum0;
        l1 = l1 * al1 + sum1;

#pragma unroll
        for (int nt = 0; nt < 16; nt++) {
            co[nt][0] *= al0; co[nt][1] *= al0;
            co[nt][2] *= al1; co[nt][3] *= al1;
        }
#pragma unroll
        for (int kb = 0; kb < 4; kb++) {
            uint32_t paH[4], paL[4];
            {
                unsigned short h0, h1, l0s, l1s;
                split2(cs[2 * kb][0], h0, l0s); split2(cs[2 * kb][1], h1, l1s);
                paH[0] = pk(h0, h1); paL[0] = pk(l0s, l1s);
                split2(cs[2 * kb][2], h0, l0s); split2(cs[2 * kb][3], h1, l1s);
                paH[1] = pk(h0, h1); paL[1] = pk(l0s, l1s);
                split2(cs[2 * kb + 1][0], h0, l0s); split2(cs[2 * kb + 1][1], h1, l1s);
                paH[2] = pk(h0, h1); paL[2] = pk(l0s, l1s);
                split2(cs[2 * kb + 1][2], h0, l0s); split2(cs[2 * kb + 1][3], h1, l1s);
                paH[3] = pk(h0, h1); paL[3] = pk(l0s, l1s);
            }
            const uint32_t vko = stg + (uint32_t)kb * 16 * QLD * 2;
#pragma unroll
            for (int half = 0; half < 2; half++) {
                uint32_t Bh[8][2], Bl[8][2];
#pragma unroll
                for (int jp = 0; jp < 4; jp++) {
                    uint32_t t[4];
                    ldm_x4_t(t, vbH[half * 4 + jp] + vko);
                    Bh[2 * jp][0] = t[0]; Bh[2 * jp][1] = t[1];
                    Bh[2 * jp + 1][0] = t[2]; Bh[2 * jp + 1][1] = t[3];
                    ldm_x4_t(t, vbL[half * 4 + jp] + vko);
                    Bl[2 * jp][0] = t[0]; Bl[2 * jp][1] = t[1];
                    Bl[2 * jp + 1][0] = t[2]; Bl[2 * jp + 1][1] = t[3];
                }
#pragma unroll
                for (int nt = 0; nt < 8; nt++) {
                    int ng = half * 8 + nt;
                    mma16816(co[ng], paH, Bh[nt][0], Bh[nt][1]);
                    mma16816(co[ng], paH, Bl[nt][0], Bl[nt][1]);
                    mma16816(co[ng], paL, Bh[nt][0], Bh[nt][1]);
                }
            }
        }
    }

    const float inv0 = 1.0f / l0, inv1 = 1.0f / l1;
    const int r0 = warp * 16 + g, r1 = r0 + 8;
#pragma unroll
    for (int nt = 0; nt < 16; nt++) {
        int col = h * HD + nt * 8 + 2 * tig;
        size_t base0 = (size_t)(b * SEQ + q0 + r0) * HID + col;
        size_t base1 = (size_t)(b * SEQ + q0 + r1) * HID + col;
        unsigned short h0, h1, l0s, l1s;
        split2(co[nt][0] * inv0, h0, l0s);
        split2(co[nt][1] * inv0, h1, l1s);
        *(uint32_t*)&g_ctx_h[base0] = pk(h0, h1);
        *(uint32_t*)&g_ctx_l[base0] = pk(l0s, l1s);
        split2(co[nt][2] * inv1, h0, l0s);
        split2(co[nt][3] * inv1, h1, l1s);
        *(uint32_t*)&g_ctx_h[base1] = pk(h0, h1);
        *(uint32_t*)&g_ctx_l[base1] = pk(l0s, l1s);
    }
}

// ---------------- launcher ---------------------------------------------------
extern "C" void kernel_launch(void* const* d_in, const int* in_sizes, int n_in,
                              void* d_out, int out_size) {
    const float* hidden = (const float*)d_in[0];
    const float* mask   = (const float*)d_in[1];
    const float* Wqkv   = (const float*)d_in[2];
    const float* bqkv   = (const float*)d_in[3];
    const float* Wout   = (const float*)d_in[4];
    const float* bout   = (const float*)d_in[5];
    float* out = (float*)d_out;

    split_kernel<<<(MROWS * HID / 4 + 255) / 256, 256>>>(hidden, 0, MROWS * HID / 4);
    split_kernel<<<(NQKV * HID / 4 + 255) / 256, 256>>>(Wqkv, 1, NQKV * HID / 4);
    split_kernel<<<(HID * HID / 4 + 255) / 256, 256>>>(Wout, 2, HID * HID / 4);
    rope_table_kernel<<<512, 256>>>();

    cudaFuncSetAttribute(mma_gemm_kernel<0>,
                         cudaFuncAttributeMaxDynamicSharedMemorySize, GEMM_SMEM);
    cudaFuncSetAttribute(mma_gemm_kernel<1>,
                         cudaFuncAttributeMaxDynamicSharedMemorySize, GEMM_SMEM);

    mma_gemm_kernel<0><<<dim3(48, 32), 256, GEMM_SMEM>>>(bqkv, nullptr);

    cudaFuncSetAttribute(attn_mma_kernel,
                         cudaFuncAttributeMaxDynamicSharedMemorySize, ATTN_SMEM);
    attn_mma_kernel<<<dim3(SEQ / 128, NH, BATCH), 256, ATTN_SMEM>>>(mask);

    mma_gemm_kernel<1><<<dim3(16, 32), 256, GEMM_SMEM>>>(bout, out);
}